// round 9
// baseline (speedup 1.0000x reference)
#include <cuda_runtime.h>
#include <math_constants.h>

#define BB 8
#define NN 50000
#define LL 512
#define RR 5
#define GPB 256                 // blocks per batch
#define WPB 8                   // warps per block
#define WARPS_PER_BATCH (GPB * WPB)   // 2048

#define H1 200
#define H2 100
#define CC 2
#define TK 25                   // w2 k-tile rows (8 tiles cover H1=200)

// partial top/bot candidates: one sorted 5+5 set per block per batch
__device__ float g_part_top[BB * GPB * RR];   // sorted descending per 5-group
__device__ float g_part_bot[BB * GPB * RR];   // sorted ascending per 5-group
// per-batch arrival counters (atomicInc wraps back to 0 -> replay-safe)
__device__ unsigned int g_count[BB];

// ---------------------------------------------------------------------------
// sorted-insertion helpers
// ---------------------------------------------------------------------------
__device__ __forceinline__ void insert_max(float* arr, float v) {
    if (v > arr[RR - 1]) {
        arr[RR - 1] = v;
#pragma unroll
        for (int j = RR - 1; j > 0; j--) {
            if (arr[j] > arr[j - 1]) {
                float t = arr[j]; arr[j] = arr[j - 1]; arr[j - 1] = t;
            }
        }
    }
}
__device__ __forceinline__ void insert_min(float* arr, float v) {
    if (v < arr[RR - 1]) {
        arr[RR - 1] = v;
#pragma unroll
        for (int j = RR - 1; j > 0; j--) {
            if (arr[j] < arr[j - 1]) {
                float t = arr[j]; arr[j] = arr[j - 1]; arr[j - 1] = t;
            }
        }
    }
}

// merge two sorted-descending 5-lists -> top 5
__device__ __forceinline__ void merge_desc5(const float* a, const float* b, float* o) {
    int i = 0, j = 0;
#pragma unroll
    for (int k = 0; k < RR; k++) {
        float av = a[i], bv = b[j];
        bool ta = (av >= bv);
        o[k] = ta ? av : bv;
        i += ta; j += !ta;
    }
}
// merge two sorted-ascending 5-lists -> bottom 5
__device__ __forceinline__ void merge_asc5(const float* a, const float* b, float* o) {
    int i = 0, j = 0;
#pragma unroll
    for (int k = 0; k < RR; k++) {
        float av = a[i], bv = b[j];
        bool ta = (av <= bv);
        o[k] = ta ? av : bv;
        i += ta; j += !ta;
    }
}

// ---------------------------------------------------------------------------
// Single fused kernel. grid = (GPB, BB), 256 threads.
// Hot path: EXACT R4 streaming scores + top/bot-5 (117.5us @ 88.6% DRAM).
// Tail: per batch, the LAST block to arrive performs tournament merge,
//       smem-tiled MLP collapse (W1@W2@W3), matvec -> out.
// __launch_bounds__(256, 8) pins regs at 32 so the hot loop keeps 8 blocks/SM.
// ---------------------------------------------------------------------------
__global__ __launch_bounds__(256, 8) void chowder_fused_kernel(
    const float* __restrict__ x,
    const float* __restrict__ conv_w,
    const float* __restrict__ conv_b,
    const float* __restrict__ w1, const float* __restrict__ b1,
    const float* __restrict__ w2, const float* __restrict__ b2,
    const float* __restrict__ w3, const float* __restrict__ b3,
    float* __restrict__ out)
{
    __shared__ float4 ws[LL / 4];                // 2 KB (hot loop)
    __shared__ float stop[WPB * RR];
    __shared__ float sbot[WPB * RR];
    // merger scratch (used only by the last block of each batch)
    // layout: [0..1280) mstop | [1280..2560) msbot | [2560..4560) sw1 |
    //         [4560..4760) sb1 | tiles reuse [0..2500) | [4760..5760) sW12 |
    //         [5760..5860) sb12
    __shared__ float sbuf[5860];                 // 23.4 KB
    __shared__ float cat[2 * RR];
    __shared__ float sWe[2 * RR * CC];
    __shared__ float sbe[CC];
    __shared__ int   sIsLast;

    const int tid  = threadIdx.x;
    const int warp = tid >> 5;
    const int lane = tid & 31;
    const int b    = blockIdx.y;

    // ================= hot streaming path (unchanged from R4) =================
    for (int i = tid; i < LL / 4; i += blockDim.x)
        ws[i] = reinterpret_cast<const float4*>(conv_w)[i];
    __syncthreads();

    float4 w0  = ws[0 * 32 + lane];
    float4 w1r = ws[1 * 32 + lane];
    float4 w2r = ws[2 * 32 + lane];
    float4 w3r = ws[3 * 32 + lane];

    const int gw = blockIdx.x * WPB + warp;
    const float cb = conv_b[0];
    const float* __restrict__ xb = x + (long long)b * NN * LL;

    float top[RR], bot[RR];
#pragma unroll
    for (int i = 0; i < RR; i++) { top[i] = -CUDART_INF_F; bot[i] = CUDART_INF_F; }

    for (int inst = gw; inst < NN; inst += WARPS_PER_BATCH) {
        const float4* __restrict__ xp =
            reinterpret_cast<const float4*>(xb + (long long)inst * LL);

        float4 v0 = xp[0 * 32 + lane];
        float4 v1 = xp[1 * 32 + lane];
        float4 v2 = xp[2 * 32 + lane];
        float4 v3 = xp[3 * 32 + lane];

        float acc = 0.0f;
        acc = fmaf(v0.x, w0.x,  acc); acc = fmaf(v0.y, w0.y,  acc);
        acc = fmaf(v0.z, w0.z,  acc); acc = fmaf(v0.w, w0.w,  acc);
        acc = fmaf(v1.x, w1r.x, acc); acc = fmaf(v1.y, w1r.y, acc);
        acc = fmaf(v1.z, w1r.z, acc); acc = fmaf(v1.w, w1r.w, acc);
        acc = fmaf(v2.x, w2r.x, acc); acc = fmaf(v2.y, w2r.y, acc);
        acc = fmaf(v2.z, w2r.z, acc); acc = fmaf(v2.w, w2r.w, acc);
        acc = fmaf(v3.x, w3r.x, acc); acc = fmaf(v3.y, w3r.y, acc);
        acc = fmaf(v3.z, w3r.z, acc); acc = fmaf(v3.w, w3r.w, acc);

#pragma unroll
        for (int o = 16; o; o >>= 1)
            acc += __shfl_xor_sync(0xffffffff, acc, o);

        if (lane == 0) {
            float v = acc + cb;
            insert_max(top, v);
            insert_min(bot, v);
        }
    }

    if (lane == 0) {
#pragma unroll
        for (int j = 0; j < RR; j++) {
            stop[warp * RR + j] = top[j];
            sbot[warp * RR + j] = bot[j];
        }
    }
    __syncthreads();

    if (tid == 0) {
        float ft[RR], fb[RR];
#pragma unroll
        for (int i = 0; i < RR; i++) { ft[i] = -CUDART_INF_F; fb[i] = CUDART_INF_F; }
        for (int i = 0; i < WPB * RR; i++) {
            insert_max(ft, stop[i]);
            insert_min(fb, sbot[i]);
        }
        float* pt = g_part_top + ((long long)b * GPB + blockIdx.x) * RR;
        float* pb = g_part_bot + ((long long)b * GPB + blockIdx.x) * RR;
#pragma unroll
        for (int j = 0; j < RR; j++) { pt[j] = ft[j]; pb[j] = fb[j]; }
    }

    // ================= arrival ticket =================
    if (tid == 0) {
        __threadfence();   // make partials visible before the ticket
        unsigned int t = atomicInc(&g_count[b], GPB - 1);
        sIsLast = (t == GPB - 1);
    }
    __syncthreads();
    if (!sIsLast) return;

    // ================= merger path (one block per batch) =================
    float* mstop = sbuf;            // 1280
    float* msbot = sbuf + 1280;     // 1280
    float* sw1   = sbuf + 2560;     // 2000
    float* sb1   = sbuf + 4560;     // 200
    float* tile  = sbuf;            // 2500 (reuses tournament region)
    float* sW12  = sbuf + 4760;     // 1000
    float* sb12  = sbuf + 5760;     // 100

    // phase 1: one coalesced staging wave (partials + w1 + b1)
    {
        const float* pt = g_part_top + (long long)b * GPB * RR;
        const float* pb = g_part_bot + (long long)b * GPB * RR;
#pragma unroll
        for (int i = tid; i < GPB * RR; i += 256) {
            mstop[i] = pt[i];
            msbot[i] = pb[i];
        }
        for (int i = tid; i < 2 * RR * H1; i += 256) sw1[i] = w1[i];
        if (tid < H1) sb1[tid] = b1[tid];
    }
    __syncthreads();

    // phase 2: tournament, 256 sorted 5-lists -> 1
    for (int cnt = GPB; cnt > 1; cnt >>= 1) {
        int half = cnt >> 1;
        if (tid < half) {
            float a[RR], c[RR], o[RR];
#pragma unroll
            for (int j = 0; j < RR; j++) { a[j] = mstop[tid * RR + j]; c[j] = mstop[(tid + half) * RR + j]; }
            merge_desc5(a, c, o);
#pragma unroll
            for (int j = 0; j < RR; j++) mstop[tid * RR + j] = o[j];

#pragma unroll
            for (int j = 0; j < RR; j++) { a[j] = msbot[tid * RR + j]; c[j] = msbot[(tid + half) * RR + j]; }
            merge_asc5(a, c, o);
#pragma unroll
            for (int j = 0; j < RR; j++) msbot[tid * RR + j] = o[j];
        }
        __syncthreads();
    }
    // cat = [min ascending, max descending]  (extract before tile overwrites)
    if (tid < RR)          cat[tid] = msbot[tid];
    else if (tid < 2 * RR) cat[tid] = mstop[tid - RR];

    // phase 3: W12 = W1@W2 via 8 smem tiles of w2 (all-smem inner loop)
    for (int i = tid; i < 2 * RR * H2; i += 256) sW12[i] = 0.0f;
    if (tid < H2) sb12[tid] = 0.0f;

    for (int t = 0; t < H1 / TK; t++) {
        __syncthreads();
        const float* w2t = w2 + t * TK * H2;
        for (int i = tid; i < TK * H2; i += 256)
            tile[i] = w2t[i];
        __syncthreads();

        if (tid < 2 * H2) {
            const int ih = tid / H2;        // i-half: 0 -> i 0..4, 1 -> i 5..9
            const int o  = tid % H2;
#pragma unroll
            for (int ii = 0; ii < RR; ii++) {
                const int i = ih * RR + ii;
                float s0 = 0.0f, s1 = 0.0f;
#pragma unroll
                for (int k = 0; k < TK - 1; k += 2) {
                    s0 = fmaf(sw1[i * H1 + t * TK + k],     tile[k * H2 + o],       s0);
                    s1 = fmaf(sw1[i * H1 + t * TK + k + 1], tile[(k + 1) * H2 + o], s1);
                }
                s0 = fmaf(sw1[i * H1 + t * TK + (TK - 1)], tile[(TK - 1) * H2 + o], s0);
                sW12[i * H2 + o] += s0 + s1;
            }
            if (ih == 0) {
                float ab = 0.0f;
#pragma unroll
                for (int k = 0; k < TK; k++)
                    ab = fmaf(sb1[t * TK + k], tile[k * H2 + o], ab);
                sb12[o] += ab;
            }
        }
    }
    __syncthreads();
    if (tid < H2) sb12[tid] += b2[tid];
    __syncthreads();

    // phase 4: fold w3 -> W_eff[10][2], b_eff[2]
    if (tid < 2 * RR * CC) {
        const int i = tid / CC, c = tid % CC;
        float a = 0.0f;
        for (int o = 0; o < H2; o++)
            a = fmaf(sW12[i * H2 + o], __ldg(&w3[o * CC + c]), a);
        sWe[tid] = a;
    }
    if (tid >= 32 && tid < 32 + CC) {
        const int c = tid - 32;
        float a = b3[c];
        for (int o = 0; o < H2; o++)
            a = fmaf(sb12[o], __ldg(&w3[o * CC + c]), a);
        sbe[c] = a;
    }
    __syncthreads();

    // phase 5: out = cat @ W_eff + b_eff
    if (tid < CC) {
        float a = sbe[tid];
#pragma unroll
        for (int i = 0; i < 2 * RR; i++)
            a = fmaf(cat[i], sWe[i * CC + tid], a);
        out[b * CC + tid] = a;
    }
}

// ---------------------------------------------------------------------------
extern "C" void kernel_launch(void* const* d_in, const int* in_sizes, int n_in,
                              void* d_out, int out_size)
{
    const float* x      = (const float*)d_in[0];
    const float* conv_w = (const float*)d_in[1];
    const float* conv_b = (const float*)d_in[2];
    const float* w1     = (const float*)d_in[3];
    const float* b1     = (const float*)d_in[4];
    const float* w2     = (const float*)d_in[5];
    const float* b2     = (const float*)d_in[6];
    const float* w3     = (const float*)d_in[7];
    const float* b3     = (const float*)d_in[8];
    float* out          = (float*)d_out;

    dim3 grid(GPB, BB);
    chowder_fused_kernel<<<grid, 256>>>(x, conv_w, conv_b,
                                        w1, b1, w2, b2, w3, b3, out);
}

// round 10
// speedup vs baseline: 1.5166x; 1.5166x over previous
#include <cuda_runtime.h>
#include <math_constants.h>

#define BB 8
#define NN 50000
#define LL 512
#define RR 5
#define GPB 148                 // blocks per batch = exactly one chip wave (148 SMs x 8 blk)
#define WPB 8                   // warps per block
#define WARPS_PER_BATCH (GPB * WPB)   // 1184
#define TOUR 256                // tournament width (partials padded with +/-inf)

#define H1 200
#define H2 100
#define CC 2
#define TK 25                   // w2 k-tile rows (8 tiles cover H1=200)

// partial top/bot candidates: one sorted 5+5 set per block per batch
__device__ float g_part_top[BB * GPB * RR];   // sorted descending per 5-group
__device__ float g_part_bot[BB * GPB * RR];   // sorted ascending per 5-group

// ---------------------------------------------------------------------------
// sorted-insertion helpers
// ---------------------------------------------------------------------------
__device__ __forceinline__ void insert_max(float* arr, float v) {
    if (v > arr[RR - 1]) {
        arr[RR - 1] = v;
#pragma unroll
        for (int j = RR - 1; j > 0; j--) {
            if (arr[j] > arr[j - 1]) {
                float t = arr[j]; arr[j] = arr[j - 1]; arr[j - 1] = t;
            }
        }
    }
}
__device__ __forceinline__ void insert_min(float* arr, float v) {
    if (v < arr[RR - 1]) {
        arr[RR - 1] = v;
#pragma unroll
        for (int j = RR - 1; j > 0; j--) {
            if (arr[j] < arr[j - 1]) {
                float t = arr[j]; arr[j] = arr[j - 1]; arr[j - 1] = t;
            }
        }
    }
}

// merge two sorted-descending 5-lists -> top 5
__device__ __forceinline__ void merge_desc5(const float* a, const float* b, float* o) {
    int i = 0, j = 0;
#pragma unroll
    for (int k = 0; k < RR; k++) {
        float av = a[i], bv = b[j];
        bool ta = (av >= bv);
        o[k] = ta ? av : bv;
        i += ta; j += !ta;
    }
}
// merge two sorted-ascending 5-lists -> bottom 5
__device__ __forceinline__ void merge_asc5(const float* a, const float* b, float* o) {
    int i = 0, j = 0;
#pragma unroll
    for (int k = 0; k < RR; k++) {
        float av = a[i], bv = b[j];
        bool ta = (av <= bv);
        o[k] = ta ? av : bv;
        i += ta; j += !ta;
    }
}

// ---------------------------------------------------------------------------
// Kernel A: scores + running top-5/bot-5. grid = (GPB, BB) = one full wave.
// Hot loop identical to proven R4 version (88.6% DRAM); only GPB changed so
// the launch is exactly 148x8 blocks = 1 wave (no wave-2 transition/imbalance).
// ---------------------------------------------------------------------------
__global__ __launch_bounds__(256) void chowder_scores_topk_kernel(
    const float* __restrict__ x,
    const float* __restrict__ conv_w,
    const float* __restrict__ conv_b)
{
    __shared__ float4 ws[LL / 4];
    __shared__ float stop[WPB * RR];
    __shared__ float sbot[WPB * RR];

    const int tid  = threadIdx.x;
    const int warp = tid >> 5;
    const int lane = tid & 31;
    const int b    = blockIdx.y;

    for (int i = tid; i < LL / 4; i += blockDim.x)
        ws[i] = reinterpret_cast<const float4*>(conv_w)[i];
    __syncthreads();

    float4 w0  = ws[0 * 32 + lane];
    float4 w1r = ws[1 * 32 + lane];
    float4 w2r = ws[2 * 32 + lane];
    float4 w3r = ws[3 * 32 + lane];

    const int gw = blockIdx.x * WPB + warp;
    const float cb = conv_b[0];
    const float* __restrict__ xb = x + (long long)b * NN * LL;

    float top[RR], bot[RR];
#pragma unroll
    for (int i = 0; i < RR; i++) { top[i] = -CUDART_INF_F; bot[i] = CUDART_INF_F; }

    for (int inst = gw; inst < NN; inst += WARPS_PER_BATCH) {
        const float4* __restrict__ xp =
            reinterpret_cast<const float4*>(xb + (long long)inst * LL);

        float4 v0 = xp[0 * 32 + lane];
        float4 v1 = xp[1 * 32 + lane];
        float4 v2 = xp[2 * 32 + lane];
        float4 v3 = xp[3 * 32 + lane];

        float acc = 0.0f;
        acc = fmaf(v0.x, w0.x,  acc); acc = fmaf(v0.y, w0.y,  acc);
        acc = fmaf(v0.z, w0.z,  acc); acc = fmaf(v0.w, w0.w,  acc);
        acc = fmaf(v1.x, w1r.x, acc); acc = fmaf(v1.y, w1r.y, acc);
        acc = fmaf(v1.z, w1r.z, acc); acc = fmaf(v1.w, w1r.w, acc);
        acc = fmaf(v2.x, w2r.x, acc); acc = fmaf(v2.y, w2r.y, acc);
        acc = fmaf(v2.z, w2r.z, acc); acc = fmaf(v2.w, w2r.w, acc);
        acc = fmaf(v3.x, w3r.x, acc); acc = fmaf(v3.y, w3r.y, acc);
        acc = fmaf(v3.z, w3r.z, acc); acc = fmaf(v3.w, w3r.w, acc);

#pragma unroll
        for (int o = 16; o; o >>= 1)
            acc += __shfl_xor_sync(0xffffffff, acc, o);

        if (lane == 0) {
            float v = acc + cb;
            insert_max(top, v);
            insert_min(bot, v);
        }
    }

    if (lane == 0) {
#pragma unroll
        for (int j = 0; j < RR; j++) {
            stop[warp * RR + j] = top[j];
            sbot[warp * RR + j] = bot[j];
        }
    }
    __syncthreads();

    if (tid == 0) {
        float ft[RR], fb[RR];
#pragma unroll
        for (int i = 0; i < RR; i++) { ft[i] = -CUDART_INF_F; fb[i] = CUDART_INF_F; }
        for (int i = 0; i < WPB * RR; i++) {
            insert_max(ft, stop[i]);
            insert_min(fb, sbot[i]);
        }
        float* pt = g_part_top + ((long long)b * GPB + blockIdx.x) * RR;
        float* pb = g_part_bot + ((long long)b * GPB + blockIdx.x) * RR;
#pragma unroll
        for (int j = 0; j < RR; j++) { pt[j] = ft[j]; pb[j] = fb[j]; }
    }
}

// ---------------------------------------------------------------------------
// Kernel B: merge + smem-tiled MLP collapse (LDS-lean). grid = BB, 256 thr.
// ---------------------------------------------------------------------------
__global__ __launch_bounds__(256) void chowder_merge_mlp_kernel(
    const float* __restrict__ w1, const float* __restrict__ b1,
    const float* __restrict__ w2, const float* __restrict__ b2,
    const float* __restrict__ w3, const float* __restrict__ b3,
    float* __restrict__ out)
{
    const int b   = blockIdx.x;
    const int tid = threadIdx.x;

    __shared__ float mstop[TOUR * RR];      // 5 KB (padded to 256 lists)
    __shared__ float msbot[TOUR * RR];      // 5 KB
    __shared__ float sw1[2 * RR * H1];      // 8 KB
    __shared__ float sb1[H1];
    __shared__ float tile[TK * H2];         // 10 KB
    __shared__ float sW12[2 * RR * H2];     // 4 KB
    __shared__ float sb12[H2];
    __shared__ float sWe[2 * RR * CC];
    __shared__ float sbe[CC];
    __shared__ float cat[2 * RR];

    // ---- phase 1: one coalesced staging wave (partials + w1 + b1) ----
    {
        const float* pt = g_part_top + (long long)b * GPB * RR;
        const float* pb = g_part_bot + (long long)b * GPB * RR;
        for (int i = tid; i < TOUR * RR; i += 256) {
            bool valid = (i < GPB * RR);
            mstop[i] = valid ? pt[i] : -CUDART_INF_F;
            msbot[i] = valid ? pb[i] :  CUDART_INF_F;
        }
        for (int i = tid; i < 2 * RR * H1; i += 256) sw1[i] = w1[i];
        if (tid < H1) sb1[tid] = b1[tid];
    }
    __syncthreads();

    // ---- phase 2: tournament, 256 sorted 5-lists -> 1 ----
    for (int cnt = TOUR; cnt > 1; cnt >>= 1) {
        int half = cnt >> 1;
        if (tid < half) {
            float a[RR], c[RR], o[RR];
#pragma unroll
            for (int j = 0; j < RR; j++) { a[j] = mstop[tid * RR + j]; c[j] = mstop[(tid + half) * RR + j]; }
            merge_desc5(a, c, o);
#pragma unroll
            for (int j = 0; j < RR; j++) mstop[tid * RR + j] = o[j];

#pragma unroll
            for (int j = 0; j < RR; j++) { a[j] = msbot[tid * RR + j]; c[j] = msbot[(tid + half) * RR + j]; }
            merge_asc5(a, c, o);
#pragma unroll
            for (int j = 0; j < RR; j++) msbot[tid * RR + j] = o[j];
        }
        __syncthreads();
    }
    if (tid < RR)          cat[tid] = msbot[tid];
    else if (tid < 2 * RR) cat[tid] = mstop[tid - RR];

    // ---- phase 3: W12 = W1@W2, k-outer, register accumulators ----
    // thread (ih, o): ih = tid/100 selects i-range [ih*5, ih*5+5), o = column.
    // Per k: 1 tile LDS + 5 broadcast sw1 LDS + 5 FMA. acc[5] in registers.
    const int ih = tid / H2;      // 0 or 1 (tid < 200)
    const int oc = tid % H2;
    float acc[RR];
    float accb = 0.0f;
#pragma unroll
    for (int i = 0; i < RR; i++) acc[i] = 0.0f;

    for (int t = 0; t < H1 / TK; t++) {
        __syncthreads();
        const float* w2t = w2 + t * TK * H2;
        for (int i = tid; i < TK * H2; i += 256)
            tile[i] = w2t[i];
        __syncthreads();

        if (tid < 2 * H2) {
#pragma unroll
            for (int k = 0; k < TK; k++) {
                const float tv = tile[k * H2 + oc];
                const int kk = t * TK + k;
#pragma unroll
                for (int ii = 0; ii < RR; ii++)
                    acc[ii] = fmaf(sw1[(ih * RR + ii) * H1 + kk], tv, acc[ii]);
                if (ih == 0)
                    accb = fmaf(sb1[kk], tv, accb);
            }
        }
    }
    __syncthreads();
    if (tid < 2 * H2) {
#pragma unroll
        for (int ii = 0; ii < RR; ii++)
            sW12[(ih * RR + ii) * H2 + oc] = acc[ii];
        if (ih == 0)
            sb12[oc] = accb + b2[oc];
    }
    __syncthreads();

    // ---- phase 4: fold w3 -> W_eff[10][2], b_eff[2] ----
    if (tid < 2 * RR * CC) {
        const int i = tid / CC, c = tid % CC;
        float a = 0.0f;
        for (int o = 0; o < H2; o++)
            a = fmaf(sW12[i * H2 + o], __ldg(&w3[o * CC + c]), a);
        sWe[tid] = a;
    }
    if (tid >= 32 && tid < 32 + CC) {
        const int c = tid - 32;
        float a = b3[c];
        for (int o = 0; o < H2; o++)
            a = fmaf(sb12[o], __ldg(&w3[o * CC + c]), a);
        sbe[c] = a;
    }
    __syncthreads();

    // ---- phase 5: out = cat @ W_eff + b_eff ----
    if (tid < CC) {
        float a = sbe[tid];
#pragma unroll
        for (int i = 0; i < 2 * RR; i++)
            a = fmaf(cat[i], sWe[i * CC + tid], a);
        out[b * CC + tid] = a;
    }
}

// ---------------------------------------------------------------------------
extern "C" void kernel_launch(void* const* d_in, const int* in_sizes, int n_in,
                              void* d_out, int out_size)
{
    const float* x      = (const float*)d_in[0];
    const float* conv_w = (const float*)d_in[1];
    const float* conv_b = (const float*)d_in[2];
    const float* w1     = (const float*)d_in[3];
    const float* b1     = (const float*)d_in[4];
    const float* w2     = (const float*)d_in[5];
    const float* b2     = (const float*)d_in[6];
    const float* w3     = (const float*)d_in[7];
    const float* b3     = (const float*)d_in[8];
    float* out          = (float*)d_out;

    dim3 grid(GPB, BB);
    chowder_scores_topk_kernel<<<grid, 256>>>(x, conv_w, conv_b);
    chowder_merge_mlp_kernel<<<BB, 256>>>(w1, b1, w2, b2, w3, b3, out);
}

// round 11
// speedup vs baseline: 1.7672x; 1.1653x over previous
#include <cuda_runtime.h>
#include <math_constants.h>

#define BB 8
#define NN 50000
#define LL 512
#define RR 5
#define GPB 256                 // blocks per batch (proven R4/R8 shape)
#define WPB 8                   // warps per block
#define WARPS_PER_BATCH (GPB * WPB)   // 2048

#define H1 200
#define H2 100
#define CC 2

// partial top/bot candidates: one sorted 5+5 set per block per batch
__device__ float g_part_top[BB * GPB * RR];   // sorted descending per 5-group
__device__ float g_part_bot[BB * GPB * RR];   // sorted ascending per 5-group

// ---------------------------------------------------------------------------
// sorted-insertion helpers
// ---------------------------------------------------------------------------
__device__ __forceinline__ void insert_max(float* arr, float v) {
    if (v > arr[RR - 1]) {
        arr[RR - 1] = v;
#pragma unroll
        for (int j = RR - 1; j > 0; j--) {
            if (arr[j] > arr[j - 1]) {
                float t = arr[j]; arr[j] = arr[j - 1]; arr[j - 1] = t;
            }
        }
    }
}
__device__ __forceinline__ void insert_min(float* arr, float v) {
    if (v < arr[RR - 1]) {
        arr[RR - 1] = v;
#pragma unroll
        for (int j = RR - 1; j > 0; j--) {
            if (arr[j] < arr[j - 1]) {
                float t = arr[j]; arr[j] = arr[j - 1]; arr[j - 1] = t;
            }
        }
    }
}

// merge two sorted-descending 5-lists -> top 5
__device__ __forceinline__ void merge_desc5(const float* a, const float* b, float* o) {
    int i = 0, j = 0;
#pragma unroll
    for (int k = 0; k < RR; k++) {
        float av = a[i], bv = b[j];
        bool ta = (av >= bv);
        o[k] = ta ? av : bv;
        i += ta; j += !ta;
    }
}
// merge two sorted-ascending 5-lists -> bottom 5
__device__ __forceinline__ void merge_asc5(const float* a, const float* b, float* o) {
    int i = 0, j = 0;
#pragma unroll
    for (int k = 0; k < RR; k++) {
        float av = a[i], bv = b[j];
        bool ta = (av <= bv);
        o[k] = ta ? av : bv;
        i += ta; j += !ta;
    }
}

// ---------------------------------------------------------------------------
// Kernel A: scores + running top-5/bot-5. grid = (GPB, BB), 256 threads.
// EXACT R4/R8 version — proven 117.5us @ 88.6% DRAM, regs=32. Do not touch.
// ---------------------------------------------------------------------------
__global__ __launch_bounds__(256) void chowder_scores_topk_kernel(
    const float* __restrict__ x,
    const float* __restrict__ conv_w,
    const float* __restrict__ conv_b)
{
    __shared__ float4 ws[LL / 4];
    __shared__ float stop[WPB * RR];
    __shared__ float sbot[WPB * RR];

    const int tid  = threadIdx.x;
    const int warp = tid >> 5;
    const int lane = tid & 31;
    const int b    = blockIdx.y;

    for (int i = tid; i < LL / 4; i += blockDim.x)
        ws[i] = reinterpret_cast<const float4*>(conv_w)[i];
    __syncthreads();

    float4 w0  = ws[0 * 32 + lane];
    float4 w1r = ws[1 * 32 + lane];
    float4 w2r = ws[2 * 32 + lane];
    float4 w3r = ws[3 * 32 + lane];

    const int gw = blockIdx.x * WPB + warp;
    const float cb = conv_b[0];
    const float* __restrict__ xb = x + (long long)b * NN * LL;

    float top[RR], bot[RR];
#pragma unroll
    for (int i = 0; i < RR; i++) { top[i] = -CUDART_INF_F; bot[i] = CUDART_INF_F; }

    for (int inst = gw; inst < NN; inst += WARPS_PER_BATCH) {
        const float4* __restrict__ xp =
            reinterpret_cast<const float4*>(xb + (long long)inst * LL);

        float4 v0 = xp[0 * 32 + lane];
        float4 v1 = xp[1 * 32 + lane];
        float4 v2 = xp[2 * 32 + lane];
        float4 v3 = xp[3 * 32 + lane];

        float acc = 0.0f;
        acc = fmaf(v0.x, w0.x,  acc); acc = fmaf(v0.y, w0.y,  acc);
        acc = fmaf(v0.z, w0.z,  acc); acc = fmaf(v0.w, w0.w,  acc);
        acc = fmaf(v1.x, w1r.x, acc); acc = fmaf(v1.y, w1r.y, acc);
        acc = fmaf(v1.z, w1r.z, acc); acc = fmaf(v1.w, w1r.w, acc);
        acc = fmaf(v2.x, w2r.x, acc); acc = fmaf(v2.y, w2r.y, acc);
        acc = fmaf(v2.z, w2r.z, acc); acc = fmaf(v2.w, w2r.w, acc);
        acc = fmaf(v3.x, w3r.x, acc); acc = fmaf(v3.y, w3r.y, acc);
        acc = fmaf(v3.z, w3r.z, acc); acc = fmaf(v3.w, w3r.w, acc);

#pragma unroll
        for (int o = 16; o; o >>= 1)
            acc += __shfl_xor_sync(0xffffffff, acc, o);

        if (lane == 0) {
            float v = acc + cb;
            insert_max(top, v);
            insert_min(bot, v);
        }
    }

    if (lane == 0) {
#pragma unroll
        for (int j = 0; j < RR; j++) {
            stop[warp * RR + j] = top[j];
            sbot[warp * RR + j] = bot[j];
        }
    }
    __syncthreads();

    if (tid == 0) {
        float ft[RR], fb[RR];
#pragma unroll
        for (int i = 0; i < RR; i++) { ft[i] = -CUDART_INF_F; fb[i] = CUDART_INF_F; }
        for (int i = 0; i < WPB * RR; i++) {
            insert_max(ft, stop[i]);
            insert_min(fb, sbot[i]);
        }
        float* pt = g_part_top + ((long long)b * GPB + blockIdx.x) * RR;
        float* pb = g_part_bot + ((long long)b * GPB + blockIdx.x) * RR;
#pragma unroll
        for (int j = 0; j < RR; j++) { pt[j] = ft[j]; pb[j] = fb[j]; }
    }
}

// ---------------------------------------------------------------------------
// Kernel B v4: merge + right-to-left MLP collapse — ZERO tile phases.
//   DRAM phase 1: partials + w1 + b1 + b2 + w3 (one coalesced wave)
//   tournament (smem/registers)
//   DRAM phase 2: W23 = w2 @ w3 — thread k reads w2 row k as 25 independent
//                 float4 loads (pipelined, no smem staging, no syncs between)
//   W_eff = w1 @ W23 (smem), b_eff = b1@W23 + b2@w3 + b3; 20-FMA matvec.
// grid = BB, 256 threads.
// ---------------------------------------------------------------------------
__global__ __launch_bounds__(256) void chowder_merge_mlp_kernel(
    const float* __restrict__ w1, const float* __restrict__ b1,
    const float* __restrict__ w2, const float* __restrict__ b2,
    const float* __restrict__ w3, const float* __restrict__ b3,
    float* __restrict__ out)
{
    const int b   = blockIdx.x;
    const int tid = threadIdx.x;

    __shared__ float mstop[GPB * RR];       // 5 KB
    __shared__ float msbot[GPB * RR];       // 5 KB
    __shared__ float sw1[2 * RR * H1];      // 8 KB  w1 [10][200]
    __shared__ float sb1[H1];
    __shared__ float sb2[H2];
    __shared__ float sw3[H2 * CC];          // 800 B
    __shared__ float sW23[H1 * CC];         // 1.6 KB  w2@w3 [200][2]
    __shared__ float sWe[2 * RR * CC];
    __shared__ float sbe[CC];
    __shared__ float cat[2 * RR];

    // ---- DRAM phase 1: one coalesced staging wave (all independent) ----
    {
        const float* pt = g_part_top + (long long)b * GPB * RR;
        const float* pb = g_part_bot + (long long)b * GPB * RR;
#pragma unroll
        for (int i = tid; i < GPB * RR; i += 256) {
            mstop[i] = pt[i];
            msbot[i] = pb[i];
        }
        for (int i = tid; i < 2 * RR * H1; i += 256) sw1[i] = w1[i];
        if (tid < H1)      sb1[tid] = b1[tid];
        if (tid < H2)      sb2[tid] = b2[tid];
        if (tid < H2 * CC) sw3[tid] = w3[tid];
    }
    __syncthreads();

    // ---- tournament: 256 sorted 5-lists -> 1, 8 levels ----
    for (int cnt = GPB; cnt > 1; cnt >>= 1) {
        int half = cnt >> 1;
        if (tid < half) {
            float a[RR], c[RR], o[RR];
#pragma unroll
            for (int j = 0; j < RR; j++) { a[j] = mstop[tid * RR + j]; c[j] = mstop[(tid + half) * RR + j]; }
            merge_desc5(a, c, o);
#pragma unroll
            for (int j = 0; j < RR; j++) mstop[tid * RR + j] = o[j];

#pragma unroll
            for (int j = 0; j < RR; j++) { a[j] = msbot[tid * RR + j]; c[j] = msbot[(tid + half) * RR + j]; }
            merge_asc5(a, c, o);
#pragma unroll
            for (int j = 0; j < RR; j++) msbot[tid * RR + j] = o[j];
        }
        __syncthreads();
    }
    if (tid < RR)          cat[tid] = msbot[tid];
    else if (tid < 2 * RR) cat[tid] = mstop[tid - RR];

    // ---- DRAM phase 2: W23[k][c] = sum_o w2[k][o] * w3[o][c] ----
    // thread k (tid<200): 25 independent float4 loads of w2 row k.
    if (tid < H1) {
        const float4* __restrict__ w2row =
            reinterpret_cast<const float4*>(w2 + tid * H2);
        float a0 = 0.0f, a1 = 0.0f;
#pragma unroll
        for (int q = 0; q < H2 / 4; q++) {
            float4 v = w2row[q];            // 25 independent LDG.128
            const int o = q * 4;
            a0 = fmaf(v.x, sw3[(o + 0) * CC + 0], a0);
            a1 = fmaf(v.x, sw3[(o + 0) * CC + 1], a1);
            a0 = fmaf(v.y, sw3[(o + 1) * CC + 0], a0);
            a1 = fmaf(v.y, sw3[(o + 1) * CC + 1], a1);
            a0 = fmaf(v.z, sw3[(o + 2) * CC + 0], a0);
            a1 = fmaf(v.z, sw3[(o + 2) * CC + 1], a1);
            a0 = fmaf(v.w, sw3[(o + 3) * CC + 0], a0);
            a1 = fmaf(v.w, sw3[(o + 3) * CC + 1], a1);
        }
        sW23[tid * CC + 0] = a0;
        sW23[tid * CC + 1] = a1;
    }
    __syncthreads();

    // ---- W_eff[i][c] = sum_k w1[i][k] * W23[k][c]  (20 threads, smem) ----
    if (tid < 2 * RR * CC) {
        const int i = tid / CC, c = tid % CC;
        float s0 = 0.0f, s1 = 0.0f;
#pragma unroll 2
        for (int k = 0; k < H1; k += 2) {
            s0 = fmaf(sw1[i * H1 + k],     sW23[k * CC + c],       s0);
            s1 = fmaf(sw1[i * H1 + k + 1], sW23[(k + 1) * CC + c], s1);
        }
        sWe[tid] = s0 + s1;
    }
    // ---- b_eff[c] = b1@W23 + b2@w3 + b3 ----
    if (tid >= 32 && tid < 32 + CC) {
        const int c = tid - 32;
        float a = b3[c];
        for (int k = 0; k < H1; k++)
            a = fmaf(sb1[k], sW23[k * CC + c], a);
        for (int o = 0; o < H2; o++)
            a = fmaf(sb2[o], sw3[o * CC + c], a);
        sbe[c] = a;
    }
    __syncthreads();

    // ---- out = cat @ W_eff + b_eff ----
    if (tid < CC) {
        float a = sbe[tid];
#pragma unroll
        for (int i = 0; i < 2 * RR; i++)
            a = fmaf(cat[i], sWe[i * CC + tid], a);
        out[b * CC + tid] = a;
    }
}

// ---------------------------------------------------------------------------
extern "C" void kernel_launch(void* const* d_in, const int* in_sizes, int n_in,
                              void* d_out, int out_size)
{
    const float* x      = (const float*)d_in[0];
    const float* conv_w = (const float*)d_in[1];
    const float* conv_b = (const float*)d_in[2];
    const float* w1     = (const float*)d_in[3];
    const float* b1     = (const float*)d_in[4];
    const float* w2     = (const float*)d_in[5];
    const float* b2     = (const float*)d_in[6];
    const float* w3     = (const float*)d_in[7];
    const float* b3     = (const float*)d_in[8];
    float* out          = (float*)d_out;

    dim3 grid(GPB, BB);
    chowder_scores_topk_kernel<<<grid, 256>>>(x, conv_w, conv_b);
    chowder_merge_mlp_kernel<<<BB, 256>>>(w1, b1, w2, b2, w3, b3, out);
}

// round 12
// speedup vs baseline: 1.7943x; 1.0153x over previous
#include <cuda_runtime.h>
#include <math_constants.h>

#define BB 8
#define NN 50000
#define LL 512
#define RR 5
#define GPB 256                 // blocks per batch (proven R4/R8 shape)
#define WPB 8                   // warps per block
#define WARPS_PER_BATCH (GPB * WPB)   // 2048

#define H1 200
#define H2 100
#define CC 2

// partial top/bot candidates: one sorted 5+5 set per block per batch
__device__ float g_part_top[BB * GPB * RR];   // sorted descending per 5-group
__device__ float g_part_bot[BB * GPB * RR];   // sorted ascending per 5-group

// ---------------------------------------------------------------------------
// sorted-insertion helpers
// ---------------------------------------------------------------------------
__device__ __forceinline__ void insert_max(float* arr, float v) {
    if (v > arr[RR - 1]) {
        arr[RR - 1] = v;
#pragma unroll
        for (int j = RR - 1; j > 0; j--) {
            if (arr[j] > arr[j - 1]) {
                float t = arr[j]; arr[j] = arr[j - 1]; arr[j - 1] = t;
            }
        }
    }
}
__device__ __forceinline__ void insert_min(float* arr, float v) {
    if (v < arr[RR - 1]) {
        arr[RR - 1] = v;
#pragma unroll
        for (int j = RR - 1; j > 0; j--) {
            if (arr[j] < arr[j - 1]) {
                float t = arr[j]; arr[j] = arr[j - 1]; arr[j - 1] = t;
            }
        }
    }
}

// merge two sorted-descending 5-lists -> top 5
__device__ __forceinline__ void merge_desc5(const float* a, const float* b, float* o) {
    int i = 0, j = 0;
#pragma unroll
    for (int k = 0; k < RR; k++) {
        float av = a[i], bv = b[j];
        bool ta = (av >= bv);
        o[k] = ta ? av : bv;
        i += ta; j += !ta;
    }
}
// merge two sorted-ascending 5-lists -> bottom 5
__device__ __forceinline__ void merge_asc5(const float* a, const float* b, float* o) {
    int i = 0, j = 0;
#pragma unroll
    for (int k = 0; k < RR; k++) {
        float av = a[i], bv = b[j];
        bool ta = (av <= bv);
        o[k] = ta ? av : bv;
        i += ta; j += !ta;
    }
}

// ---------------------------------------------------------------------------
// Kernel A: scores + running top-5/bot-5. grid = (GPB, BB), 256 threads.
// EXACT R4/R8 version — proven 117.5us @ 88.6% DRAM, regs=32. Do not touch.
// ---------------------------------------------------------------------------
__global__ __launch_bounds__(256) void chowder_scores_topk_kernel(
    const float* __restrict__ x,
    const float* __restrict__ conv_w,
    const float* __restrict__ conv_b)
{
    __shared__ float4 ws[LL / 4];
    __shared__ float stop[WPB * RR];
    __shared__ float sbot[WPB * RR];

    const int tid  = threadIdx.x;
    const int warp = tid >> 5;
    const int lane = tid & 31;
    const int b    = blockIdx.y;

    for (int i = tid; i < LL / 4; i += blockDim.x)
        ws[i] = reinterpret_cast<const float4*>(conv_w)[i];
    __syncthreads();

    float4 w0  = ws[0 * 32 + lane];
    float4 w1r = ws[1 * 32 + lane];
    float4 w2r = ws[2 * 32 + lane];
    float4 w3r = ws[3 * 32 + lane];

    const int gw = blockIdx.x * WPB + warp;
    const float cb = conv_b[0];
    const float* __restrict__ xb = x + (long long)b * NN * LL;

    float top[RR], bot[RR];
#pragma unroll
    for (int i = 0; i < RR; i++) { top[i] = -CUDART_INF_F; bot[i] = CUDART_INF_F; }

    for (int inst = gw; inst < NN; inst += WARPS_PER_BATCH) {
        const float4* __restrict__ xp =
            reinterpret_cast<const float4*>(xb + (long long)inst * LL);

        float4 v0 = xp[0 * 32 + lane];
        float4 v1 = xp[1 * 32 + lane];
        float4 v2 = xp[2 * 32 + lane];
        float4 v3 = xp[3 * 32 + lane];

        float acc = 0.0f;
        acc = fmaf(v0.x, w0.x,  acc); acc = fmaf(v0.y, w0.y,  acc);
        acc = fmaf(v0.z, w0.z,  acc); acc = fmaf(v0.w, w0.w,  acc);
        acc = fmaf(v1.x, w1r.x, acc); acc = fmaf(v1.y, w1r.y, acc);
        acc = fmaf(v1.z, w1r.z, acc); acc = fmaf(v1.w, w1r.w, acc);
        acc = fmaf(v2.x, w2r.x, acc); acc = fmaf(v2.y, w2r.y, acc);
        acc = fmaf(v2.z, w2r.z, acc); acc = fmaf(v2.w, w2r.w, acc);
        acc = fmaf(v3.x, w3r.x, acc); acc = fmaf(v3.y, w3r.y, acc);
        acc = fmaf(v3.z, w3r.z, acc); acc = fmaf(v3.w, w3r.w, acc);

#pragma unroll
        for (int o = 16; o; o >>= 1)
            acc += __shfl_xor_sync(0xffffffff, acc, o);

        if (lane == 0) {
            float v = acc + cb;
            insert_max(top, v);
            insert_min(bot, v);
        }
    }

    if (lane == 0) {
#pragma unroll
        for (int j = 0; j < RR; j++) {
            stop[warp * RR + j] = top[j];
            sbot[warp * RR + j] = bot[j];
        }
    }
    __syncthreads();

    if (tid == 0) {
        float ft[RR], fb[RR];
#pragma unroll
        for (int i = 0; i < RR; i++) { ft[i] = -CUDART_INF_F; fb[i] = CUDART_INF_F; }
        for (int i = 0; i < WPB * RR; i++) {
            insert_max(ft, stop[i]);
            insert_min(fb, sbot[i]);
        }
        float* pt = g_part_top + ((long long)b * GPB + blockIdx.x) * RR;
        float* pb = g_part_bot + ((long long)b * GPB + blockIdx.x) * RR;
#pragma unroll
        for (int j = 0; j < RR; j++) { pt[j] = ft[j]; pb[j] = fb[j]; }
    }
}

// ---------------------------------------------------------------------------
// Kernel B v5: merge + right-to-left MLP collapse, parallel tail reductions.
//   DRAM phase 1: partials + w1 + b1 + b2 + w3 (one coalesced wave)
//   tournament (smem/registers, 8 levels)
//   DRAM phase 2: W23 = w2 @ w3 (200 threads x 25 independent float4 loads)
//   W_eff: 160 threads (20 outputs x 8 lanes, depth-25 + width-8 shuffle)
//   b_eff: 64 threads  (2 ch x 32 lanes, depth ~11 + width-32 shuffle)
//   out = cat @ W_eff + b_eff
// grid = BB, 256 threads.
// ---------------------------------------------------------------------------
__global__ __launch_bounds__(256) void chowder_merge_mlp_kernel(
    const float* __restrict__ w1, const float* __restrict__ b1,
    const float* __restrict__ w2, const float* __restrict__ b2,
    const float* __restrict__ w3, const float* __restrict__ b3,
    float* __restrict__ out)
{
    const int b   = blockIdx.x;
    const int tid = threadIdx.x;

    __shared__ float mstop[GPB * RR];       // 5 KB
    __shared__ float msbot[GPB * RR];       // 5 KB
    __shared__ float sw1[2 * RR * H1];      // 8 KB  w1 [10][200]
    __shared__ float sb1[H1];
    __shared__ float sb2[H2];
    __shared__ float sw3[H2 * CC];          // 800 B
    __shared__ float sW23[H1 * CC];         // 1.6 KB  w2@w3 [200][2]
    __shared__ float sWe[2 * RR * CC];
    __shared__ float sbe[CC];
    __shared__ float cat[2 * RR];

    // ---- DRAM phase 1: one coalesced staging wave (all independent) ----
    {
        const float* pt = g_part_top + (long long)b * GPB * RR;
        const float* pb = g_part_bot + (long long)b * GPB * RR;
#pragma unroll
        for (int i = tid; i < GPB * RR; i += 256) {
            mstop[i] = pt[i];
            msbot[i] = pb[i];
        }
        for (int i = tid; i < 2 * RR * H1; i += 256) sw1[i] = w1[i];
        if (tid < H1)      sb1[tid] = b1[tid];
        if (tid < H2)      sb2[tid] = b2[tid];
        if (tid < H2 * CC) sw3[tid] = w3[tid];
    }
    __syncthreads();

    // ---- tournament: 256 sorted 5-lists -> 1, 8 levels ----
    for (int cnt = GPB; cnt > 1; cnt >>= 1) {
        int half = cnt >> 1;
        if (tid < half) {
            float a[RR], c[RR], o[RR];
#pragma unroll
            for (int j = 0; j < RR; j++) { a[j] = mstop[tid * RR + j]; c[j] = mstop[(tid + half) * RR + j]; }
            merge_desc5(a, c, o);
#pragma unroll
            for (int j = 0; j < RR; j++) mstop[tid * RR + j] = o[j];

#pragma unroll
            for (int j = 0; j < RR; j++) { a[j] = msbot[tid * RR + j]; c[j] = msbot[(tid + half) * RR + j]; }
            merge_asc5(a, c, o);
#pragma unroll
            for (int j = 0; j < RR; j++) msbot[tid * RR + j] = o[j];
        }
        __syncthreads();
    }
    if (tid < RR)          cat[tid] = msbot[tid];
    else if (tid < 2 * RR) cat[tid] = mstop[tid - RR];

    // ---- DRAM phase 2: W23[k][c] = sum_o w2[k][o] * w3[o][c] ----
    if (tid < H1) {
        const float4* __restrict__ w2row =
            reinterpret_cast<const float4*>(w2 + tid * H2);
        float a0 = 0.0f, a1 = 0.0f;
#pragma unroll
        for (int q = 0; q < H2 / 4; q++) {
            float4 v = w2row[q];            // 25 independent LDG.128
            const int o = q * 4;
            a0 = fmaf(v.x, sw3[(o + 0) * CC + 0], a0);
            a1 = fmaf(v.x, sw3[(o + 0) * CC + 1], a1);
            a0 = fmaf(v.y, sw3[(o + 1) * CC + 0], a0);
            a1 = fmaf(v.y, sw3[(o + 1) * CC + 1], a1);
            a0 = fmaf(v.z, sw3[(o + 2) * CC + 0], a0);
            a1 = fmaf(v.z, sw3[(o + 2) * CC + 1], a1);
            a0 = fmaf(v.w, sw3[(o + 3) * CC + 0], a0);
            a1 = fmaf(v.w, sw3[(o + 3) * CC + 1], a1);
        }
        sW23[tid * CC + 0] = a0;
        sW23[tid * CC + 1] = a1;
    }
    __syncthreads();

    // ---- W_eff: 20 outputs x 8 lanes, depth 25 + width-8 shuffle reduce ----
    if (tid < 160) {
        const int g = tid >> 3;         // output index 0..19 -> (i, c)
        const int r = tid & 7;          // lane within group
        const int i = g / CC, c = g % CC;
        float s = 0.0f;
#pragma unroll
        for (int k = r; k < H1; k += 8)
            s = fmaf(sw1[i * H1 + k], sW23[k * CC + c], s);
#pragma unroll
        for (int o2 = 4; o2; o2 >>= 1)
            s += __shfl_down_sync(0xffffffff, s, o2, 8);
        if (r == 0) sWe[g] = s;
    }
    // ---- b_eff: 2 channels x 32 lanes, width-32 shuffle reduce ----
    else if (tid < 224) {
        const int c = (tid - 160) >> 5;   // 0 or 1
        const int l = (tid - 160) & 31;
        float s = 0.0f;
        for (int k = l; k < H1; k += 32)
            s = fmaf(sb1[k], sW23[k * CC + c], s);
        for (int o = l; o < H2; o += 32)
            s = fmaf(sb2[o], sw3[o * CC + c], s);
#pragma unroll
        for (int o2 = 16; o2; o2 >>= 1)
            s += __shfl_down_sync(0xffffffff, s, o2);
        if (l == 0) sbe[c] = s + b3[c];
    }
    __syncthreads();

    // ---- out = cat @ W_eff + b_eff ----
    if (tid < CC) {
        float a = sbe[tid];
#pragma unroll
        for (int i = 0; i < 2 * RR; i++)
            a = fmaf(cat[i], sWe[i * CC + tid], a);
        out[b * CC + tid] = a;
    }
}

// ---------------------------------------------------------------------------
extern "C" void kernel_launch(void* const* d_in, const int* in_sizes, int n_in,
                              void* d_out, int out_size)
{
    const float* x      = (const float*)d_in[0];
    const float* conv_w = (const float*)d_in[1];
    const float* conv_b = (const float*)d_in[2];
    const float* w1     = (const float*)d_in[3];
    const float* b1     = (const float*)d_in[4];
    const float* w2     = (const float*)d_in[5];
    const float* b2     = (const float*)d_in[6];
    const float* w3     = (const float*)d_in[7];
    const float* b3     = (const float*)d_in[8];
    float* out          = (float*)d_out;

    dim3 grid(GPB, BB);
    chowder_scores_topk_kernel<<<grid, 256>>>(x, conv_w, conv_b);
    chowder_merge_mlp_kernel<<<BB, 256>>>(w1, b1, w2, b2, w3, b3, out);
}

// round 13
// speedup vs baseline: 1.8318x; 1.0209x over previous
#include <cuda_runtime.h>
#include <math_constants.h>

#define BB 8
#define NN 50000
#define LL 512
#define RR 5
#define GPB 256                 // blocks per batch (proven R4/R8 shape)
#define WPB 8                   // warps per block
#define WARPS_PER_BATCH (GPB * WPB)   // 2048

#define H1 200
#define H2 100
#define CC 2

// partial top/bot candidates: one sorted 5+5 set per block per batch
__device__ float g_part_top[BB * GPB * RR];   // sorted descending per 5-group
__device__ float g_part_bot[BB * GPB * RR];   // sorted ascending per 5-group

// ---------------------------------------------------------------------------
// sorted-insertion helpers
// ---------------------------------------------------------------------------
__device__ __forceinline__ void insert_max(float* arr, float v) {
    if (v > arr[RR - 1]) {
        arr[RR - 1] = v;
#pragma unroll
        for (int j = RR - 1; j > 0; j--) {
            if (arr[j] > arr[j - 1]) {
                float t = arr[j]; arr[j] = arr[j - 1]; arr[j - 1] = t;
            }
        }
    }
}
__device__ __forceinline__ void insert_min(float* arr, float v) {
    if (v < arr[RR - 1]) {
        arr[RR - 1] = v;
#pragma unroll
        for (int j = RR - 1; j > 0; j--) {
            if (arr[j] < arr[j - 1]) {
                float t = arr[j]; arr[j] = arr[j - 1]; arr[j - 1] = t;
            }
        }
    }
}

// merge two sorted-descending 5-lists -> top 5
__device__ __forceinline__ void merge_desc5(const float* a, const float* b, float* o) {
    int i = 0, j = 0;
#pragma unroll
    for (int k = 0; k < RR; k++) {
        float av = a[i], bv = b[j];
        bool ta = (av >= bv);
        o[k] = ta ? av : bv;
        i += ta; j += !ta;
    }
}
// merge two sorted-ascending 5-lists -> bottom 5
__device__ __forceinline__ void merge_asc5(const float* a, const float* b, float* o) {
    int i = 0, j = 0;
#pragma unroll
    for (int k = 0; k < RR; k++) {
        float av = a[i], bv = b[j];
        bool ta = (av <= bv);
        o[k] = ta ? av : bv;
        i += ta; j += !ta;
    }
}

// ---------------------------------------------------------------------------
// Kernel A: scores + running top-5/bot-5. grid = (GPB, BB), 256 threads.
// EXACT R4/R8 version — proven 117.5us @ 88.6% DRAM, regs=32. Do not touch.
// ---------------------------------------------------------------------------
__global__ __launch_bounds__(256) void chowder_scores_topk_kernel(
    const float* __restrict__ x,
    const float* __restrict__ conv_w,
    const float* __restrict__ conv_b)
{
    __shared__ float4 ws[LL / 4];
    __shared__ float stop[WPB * RR];
    __shared__ float sbot[WPB * RR];

    const int tid  = threadIdx.x;
    const int warp = tid >> 5;
    const int lane = tid & 31;
    const int b    = blockIdx.y;

    for (int i = tid; i < LL / 4; i += blockDim.x)
        ws[i] = reinterpret_cast<const float4*>(conv_w)[i];
    __syncthreads();

    float4 w0  = ws[0 * 32 + lane];
    float4 w1r = ws[1 * 32 + lane];
    float4 w2r = ws[2 * 32 + lane];
    float4 w3r = ws[3 * 32 + lane];

    const int gw = blockIdx.x * WPB + warp;
    const float cb = conv_b[0];
    const float* __restrict__ xb = x + (long long)b * NN * LL;

    float top[RR], bot[RR];
#pragma unroll
    for (int i = 0; i < RR; i++) { top[i] = -CUDART_INF_F; bot[i] = CUDART_INF_F; }

    for (int inst = gw; inst < NN; inst += WARPS_PER_BATCH) {
        const float4* __restrict__ xp =
            reinterpret_cast<const float4*>(xb + (long long)inst * LL);

        float4 v0 = xp[0 * 32 + lane];
        float4 v1 = xp[1 * 32 + lane];
        float4 v2 = xp[2 * 32 + lane];
        float4 v3 = xp[3 * 32 + lane];

        float acc = 0.0f;
        acc = fmaf(v0.x, w0.x,  acc); acc = fmaf(v0.y, w0.y,  acc);
        acc = fmaf(v0.z, w0.z,  acc); acc = fmaf(v0.w, w0.w,  acc);
        acc = fmaf(v1.x, w1r.x, acc); acc = fmaf(v1.y, w1r.y, acc);
        acc = fmaf(v1.z, w1r.z, acc); acc = fmaf(v1.w, w1r.w, acc);
        acc = fmaf(v2.x, w2r.x, acc); acc = fmaf(v2.y, w2r.y, acc);
        acc = fmaf(v2.z, w2r.z, acc); acc = fmaf(v2.w, w2r.w, acc);
        acc = fmaf(v3.x, w3r.x, acc); acc = fmaf(v3.y, w3r.y, acc);
        acc = fmaf(v3.z, w3r.z, acc); acc = fmaf(v3.w, w3r.w, acc);

#pragma unroll
        for (int o = 16; o; o >>= 1)
            acc += __shfl_xor_sync(0xffffffff, acc, o);

        if (lane == 0) {
            float v = acc + cb;
            insert_max(top, v);
            insert_min(bot, v);
        }
    }

    if (lane == 0) {
#pragma unroll
        for (int j = 0; j < RR; j++) {
            stop[warp * RR + j] = top[j];
            sbot[warp * RR + j] = bot[j];
        }
    }
    __syncthreads();

    if (tid == 0) {
        float ft[RR], fb[RR];
#pragma unroll
        for (int i = 0; i < RR; i++) { ft[i] = -CUDART_INF_F; fb[i] = CUDART_INF_F; }
        for (int i = 0; i < WPB * RR; i++) {
            insert_max(ft, stop[i]);
            insert_min(fb, sbot[i]);
        }
        float* pt = g_part_top + ((long long)b * GPB + blockIdx.x) * RR;
        float* pb = g_part_bot + ((long long)b * GPB + blockIdx.x) * RR;
#pragma unroll
        for (int j = 0; j < RR; j++) { pt[j] = ft[j]; pb[j] = fb[j]; }
    }
}

// ---------------------------------------------------------------------------
// Kernel B v6: register-batched staging (all LDGs issued independently in one
// wave), tournament, W23 = w2@w3, parallel W_eff/b_eff, matvec. grid = BB.
// ---------------------------------------------------------------------------
__global__ __launch_bounds__(256) void chowder_merge_mlp_kernel(
    const float* __restrict__ w1, const float* __restrict__ b1,
    const float* __restrict__ w2, const float* __restrict__ b2,
    const float* __restrict__ w3, const float* __restrict__ b3,
    float* __restrict__ out)
{
    const int b   = blockIdx.x;
    const int tid = threadIdx.x;

    __shared__ float mstop[GPB * RR];       // 5 KB
    __shared__ float msbot[GPB * RR];       // 5 KB
    __shared__ float sw1[2 * RR * H1];      // 8 KB  w1 [10][200]
    __shared__ float sb1[H1];
    __shared__ float sb2[H2];
    __shared__ float sw3[H2 * CC];          // 800 B
    __shared__ float sW23[H1 * CC];         // 1.6 KB  w2@w3 [200][2]
    __shared__ float sWe[2 * RR * CC];
    __shared__ float sbe[CC];
    __shared__ float cat[2 * RR];

    // ---- DRAM phase 1: register-batched staging (ONE latency wave) ----
    // All loads below are independent; compile-time trip counts so ptxas
    // front-batches the LDGs before any store.
    {
        const float* pt = g_part_top + (long long)b * GPB * RR;
        const float* pb = g_part_bot + (long long)b * GPB * RR;

        float rt[5], rb[5];                 // 1280/256 = 5 exactly
#pragma unroll
        for (int k = 0; k < 5; k++) {
            rt[k] = pt[tid + k * 256];
            rb[k] = pb[tid + k * 256];
        }
        float rw[8];                        // 2000 = 7*256 + 208 (predicated)
#pragma unroll
        for (int k = 0; k < 8; k++) {
            const int idx = tid + k * 256;
            rw[k] = (idx < 2 * RR * H1) ? w1[idx] : 0.0f;
        }
        float rb1  = (tid < H1)      ? b1[tid] : 0.0f;
        float rb2v = (tid < H2)      ? b2[tid] : 0.0f;
        float rw3  = (tid < H2 * CC) ? w3[tid] : 0.0f;

#pragma unroll
        for (int k = 0; k < 5; k++) {
            mstop[tid + k * 256] = rt[k];
            msbot[tid + k * 256] = rb[k];
        }
#pragma unroll
        for (int k = 0; k < 8; k++) {
            const int idx = tid + k * 256;
            if (idx < 2 * RR * H1) sw1[idx] = rw[k];
        }
        if (tid < H1)      sb1[tid] = rb1;
        if (tid < H2)      sb2[tid] = rb2v;
        if (tid < H2 * CC) sw3[tid] = rw3;
    }
    __syncthreads();

    // ---- tournament: 256 sorted 5-lists -> 1, 8 levels ----
    for (int cnt = GPB; cnt > 1; cnt >>= 1) {
        int half = cnt >> 1;
        if (tid < half) {
            float a[RR], c[RR], o[RR];
#pragma unroll
            for (int j = 0; j < RR; j++) { a[j] = mstop[tid * RR + j]; c[j] = mstop[(tid + half) * RR + j]; }
            merge_desc5(a, c, o);
#pragma unroll
            for (int j = 0; j < RR; j++) mstop[tid * RR + j] = o[j];

#pragma unroll
            for (int j = 0; j < RR; j++) { a[j] = msbot[tid * RR + j]; c[j] = msbot[(tid + half) * RR + j]; }
            merge_asc5(a, c, o);
#pragma unroll
            for (int j = 0; j < RR; j++) msbot[tid * RR + j] = o[j];
        }
        __syncthreads();
    }
    if (tid < RR)          cat[tid] = msbot[tid];
    else if (tid < 2 * RR) cat[tid] = mstop[tid - RR];

    // ---- DRAM phase 2: W23[k][c] = sum_o w2[k][o] * w3[o][c] ----
    // 200 threads x 25 independent float4 loads (already batched).
    if (tid < H1) {
        const float4* __restrict__ w2row =
            reinterpret_cast<const float4*>(w2 + tid * H2);
        float a0 = 0.0f, a1 = 0.0f;
#pragma unroll
        for (int q = 0; q < H2 / 4; q++) {
            float4 v = w2row[q];
            const int o = q * 4;
            a0 = fmaf(v.x, sw3[(o + 0) * CC + 0], a0);
            a1 = fmaf(v.x, sw3[(o + 0) * CC + 1], a1);
            a0 = fmaf(v.y, sw3[(o + 1) * CC + 0], a0);
            a1 = fmaf(v.y, sw3[(o + 1) * CC + 1], a1);
            a0 = fmaf(v.z, sw3[(o + 2) * CC + 0], a0);
            a1 = fmaf(v.z, sw3[(o + 2) * CC + 1], a1);
            a0 = fmaf(v.w, sw3[(o + 3) * CC + 0], a0);
            a1 = fmaf(v.w, sw3[(o + 3) * CC + 1], a1);
        }
        sW23[tid * CC + 0] = a0;
        sW23[tid * CC + 1] = a1;
    }
    __syncthreads();

    // ---- W_eff: 20 outputs x 8 lanes, depth 25 + width-8 shuffle reduce ----
    if (tid < 160) {
        const int g = tid >> 3;
        const int r = tid & 7;
        const int i = g / CC, c = g % CC;
        float s = 0.0f;
#pragma unroll
        for (int k = r; k < H1; k += 8)
            s = fmaf(sw1[i * H1 + k], sW23[k * CC + c], s);
#pragma unroll
        for (int o2 = 4; o2; o2 >>= 1)
            s += __shfl_down_sync(0xffffffff, s, o2, 8);
        if (r == 0) sWe[g] = s;
    }
    // ---- b_eff: 2 channels x 32 lanes, width-32 shuffle reduce ----
    else if (tid < 224) {
        const int c = (tid - 160) >> 5;
        const int l = (tid - 160) & 31;
        float s = 0.0f;
        for (int k = l; k < H1; k += 32)
            s = fmaf(sb1[k], sW23[k * CC + c], s);
        for (int o = l; o < H2; o += 32)
            s = fmaf(sb2[o], sw3[o * CC + c], s);
#pragma unroll
        for (int o2 = 16; o2; o2 >>= 1)
            s += __shfl_down_sync(0xffffffff, s, o2);
        if (l == 0) sbe[c] = s + b3[c];
    }
    __syncthreads();

    // ---- out = cat @ W_eff + b_eff ----
    if (tid < CC) {
        float a = sbe[tid];
#pragma unroll
        for (int i = 0; i < 2 * RR; i++)
            a = fmaf(cat[i], sWe[i * CC + tid], a);
        out[b * CC + tid] = a;
    }
}

// ---------------------------------------------------------------------------
extern "C" void kernel_launch(void* const* d_in, const int* in_sizes, int n_in,
                              void* d_out, int out_size)
{
    const float* x      = (const float*)d_in[0];
    const float* conv_w = (const float*)d_in[1];
    const float* conv_b = (const float*)d_in[2];
    const float* w1     = (const float*)d_in[3];
    const float* b1     = (const float*)d_in[4];
    const float* w2     = (const float*)d_in[5];
    const float* b2     = (const float*)d_in[6];
    const float* w3     = (const float*)d_in[7];
    const float* b3     = (const float*)d_in[8];
    float* out          = (float*)d_out;

    dim3 grid(GPB, BB);
    chowder_scores_topk_kernel<<<grid, 256>>>(x, conv_w, conv_b);
    chowder_merge_mlp_kernel<<<BB, 256>>>(w1, b1, w2, b2, w3, b3, out);
}

// round 14
// speedup vs baseline: 1.8827x; 1.0278x over previous
#include <cuda_runtime.h>
#include <math_constants.h>

#define BB 8
#define NN 50000
#define LL 512
#define RR 5
#define GPB 256                 // blocks per batch (proven R4/R8 shape)
#define WPB 8                   // warps per block
#define WARPS_PER_BATCH (GPB * WPB)   // 2048

#define H1 200
#define H2 100
#define CC 2

// partial top/bot candidates: one sorted 5+5 set per block per batch
__device__ float g_part_top[BB * GPB * RR];   // sorted descending per 5-group
__device__ float g_part_bot[BB * GPB * RR];   // sorted ascending per 5-group

// ---------------------------------------------------------------------------
// sorted-insertion helpers
// ---------------------------------------------------------------------------
__device__ __forceinline__ void insert_max(float* arr, float v) {
    if (v > arr[RR - 1]) {
        arr[RR - 1] = v;
#pragma unroll
        for (int j = RR - 1; j > 0; j--) {
            if (arr[j] > arr[j - 1]) {
                float t = arr[j]; arr[j] = arr[j - 1]; arr[j - 1] = t;
            }
        }
    }
}
__device__ __forceinline__ void insert_min(float* arr, float v) {
    if (v < arr[RR - 1]) {
        arr[RR - 1] = v;
#pragma unroll
        for (int j = RR - 1; j > 0; j--) {
            if (arr[j] < arr[j - 1]) {
                float t = arr[j]; arr[j] = arr[j - 1]; arr[j - 1] = t;
            }
        }
    }
}

// merge two sorted-descending 5-lists -> top 5
__device__ __forceinline__ void merge_desc5(const float* a, const float* b, float* o) {
    int i = 0, j = 0;
#pragma unroll
    for (int k = 0; k < RR; k++) {
        float av = a[i], bv = b[j];
        bool ta = (av >= bv);
        o[k] = ta ? av : bv;
        i += ta; j += !ta;
    }
}
// merge two sorted-ascending 5-lists -> bottom 5
__device__ __forceinline__ void merge_asc5(const float* a, const float* b, float* o) {
    int i = 0, j = 0;
#pragma unroll
    for (int k = 0; k < RR; k++) {
        float av = a[i], bv = b[j];
        bool ta = (av <= bv);
        o[k] = ta ? av : bv;
        i += ta; j += !ta;
    }
}

// ---------------------------------------------------------------------------
// Kernel A: scores + running top-5/bot-5. grid = (GPB, BB), 256 threads.
// EXACT R4/R8 version — proven 117.5us @ 88.6% DRAM, regs=32. Do not touch.
// ---------------------------------------------------------------------------
__global__ __launch_bounds__(256) void chowder_scores_topk_kernel(
    const float* __restrict__ x,
    const float* __restrict__ conv_w,
    const float* __restrict__ conv_b)
{
    __shared__ float4 ws[LL / 4];
    __shared__ float stop[WPB * RR];
    __shared__ float sbot[WPB * RR];

    const int tid  = threadIdx.x;
    const int warp = tid >> 5;
    const int lane = tid & 31;
    const int b    = blockIdx.y;

    for (int i = tid; i < LL / 4; i += blockDim.x)
        ws[i] = reinterpret_cast<const float4*>(conv_w)[i];
    __syncthreads();

    float4 w0  = ws[0 * 32 + lane];
    float4 w1r = ws[1 * 32 + lane];
    float4 w2r = ws[2 * 32 + lane];
    float4 w3r = ws[3 * 32 + lane];

    const int gw = blockIdx.x * WPB + warp;
    const float cb = conv_b[0];
    const float* __restrict__ xb = x + (long long)b * NN * LL;

    float top[RR], bot[RR];
#pragma unroll
    for (int i = 0; i < RR; i++) { top[i] = -CUDART_INF_F; bot[i] = CUDART_INF_F; }

    for (int inst = gw; inst < NN; inst += WARPS_PER_BATCH) {
        const float4* __restrict__ xp =
            reinterpret_cast<const float4*>(xb + (long long)inst * LL);

        float4 v0 = xp[0 * 32 + lane];
        float4 v1 = xp[1 * 32 + lane];
        float4 v2 = xp[2 * 32 + lane];
        float4 v3 = xp[3 * 32 + lane];

        float acc = 0.0f;
        acc = fmaf(v0.x, w0.x,  acc); acc = fmaf(v0.y, w0.y,  acc);
        acc = fmaf(v0.z, w0.z,  acc); acc = fmaf(v0.w, w0.w,  acc);
        acc = fmaf(v1.x, w1r.x, acc); acc = fmaf(v1.y, w1r.y, acc);
        acc = fmaf(v1.z, w1r.z, acc); acc = fmaf(v1.w, w1r.w, acc);
        acc = fmaf(v2.x, w2r.x, acc); acc = fmaf(v2.y, w2r.y, acc);
        acc = fmaf(v2.z, w2r.z, acc); acc = fmaf(v2.w, w2r.w, acc);
        acc = fmaf(v3.x, w3r.x, acc); acc = fmaf(v3.y, w3r.y, acc);
        acc = fmaf(v3.z, w3r.z, acc); acc = fmaf(v3.w, w3r.w, acc);

#pragma unroll
        for (int o = 16; o; o >>= 1)
            acc += __shfl_xor_sync(0xffffffff, acc, o);

        if (lane == 0) {
            float v = acc + cb;
            insert_max(top, v);
            insert_min(bot, v);
        }
    }

    if (lane == 0) {
#pragma unroll
        for (int j = 0; j < RR; j++) {
            stop[warp * RR + j] = top[j];
            sbot[warp * RR + j] = bot[j];
        }
    }
    __syncthreads();

    if (tid == 0) {
        float ft[RR], fb[RR];
#pragma unroll
        for (int i = 0; i < RR; i++) { ft[i] = -CUDART_INF_F; fb[i] = CUDART_INF_F; }
        for (int i = 0; i < WPB * RR; i++) {
            insert_max(ft, stop[i]);
            insert_min(fb, sbot[i]);
        }
        float* pt = g_part_top + ((long long)b * GPB + blockIdx.x) * RR;
        float* pb = g_part_bot + ((long long)b * GPB + blockIdx.x) * RR;
#pragma unroll
        for (int j = 0; j < RR; j++) { pt[j] = ft[j]; pb[j] = fb[j]; }
    }
}

// ---------------------------------------------------------------------------
// Kernel B v7: overlapped specialization. grid = BB, 256 threads.
//   all:        register-batched staging wave (partials+w1+b1+b2+w3)
//   tid>=128:   issue w2-row LDGs BEFORE the block sync (wave overlaps sync)
//   tid<128:    8-level tournament on named barrier 1
//   tid>=128:   W23 rows (concurrent with tournament)
//   full sync -> W_eff / b_eff shuffle reductions -> 20-FMA matvec
// ---------------------------------------------------------------------------
__global__ __launch_bounds__(256) void chowder_merge_mlp_kernel(
    const float* __restrict__ w1, const float* __restrict__ b1,
    const float* __restrict__ w2, const float* __restrict__ b2,
    const float* __restrict__ w3, const float* __restrict__ b3,
    float* __restrict__ out)
{
    const int b   = blockIdx.x;
    const int tid = threadIdx.x;

    __shared__ float mstop[GPB * RR];       // 5 KB
    __shared__ float msbot[GPB * RR];       // 5 KB
    __shared__ float sw1[2 * RR * H1];      // 8 KB  w1 [10][200]
    __shared__ float sb1[H1];
    __shared__ float sb2[H2];
    __shared__ float sw3[H2 * CC];          // 800 B
    __shared__ float sW23[H1 * CC];         // 1.6 KB  w2@w3 [200][2]
    __shared__ float sWe[2 * RR * CC];
    __shared__ float sbe[CC];
    __shared__ float cat[2 * RR];

    // ---- staging: register-batched (one latency wave), all 256 threads ----
    {
        const float* pt = g_part_top + (long long)b * GPB * RR;
        const float* pb = g_part_bot + (long long)b * GPB * RR;

        float rt[5], rb[5];                 // 1280/256 = 5 exactly
#pragma unroll
        for (int k = 0; k < 5; k++) {
            rt[k] = pt[tid + k * 256];
            rb[k] = pb[tid + k * 256];
        }
        float rw[8];                        // 2000 = 7*256 + 208 (predicated)
#pragma unroll
        for (int k = 0; k < 8; k++) {
            const int idx = tid + k * 256;
            rw[k] = (idx < 2 * RR * H1) ? w1[idx] : 0.0f;
        }
        float rb1  = (tid < H1)      ? b1[tid] : 0.0f;
        float rb2v = (tid < H2)      ? b2[tid] : 0.0f;
        float rw3  = (tid < H2 * CC) ? w3[tid] : 0.0f;

#pragma unroll
        for (int k = 0; k < 5; k++) {
            mstop[tid + k * 256] = rt[k];
            msbot[tid + k * 256] = rb[k];
        }
#pragma unroll
        for (int k = 0; k < 8; k++) {
            const int idx = tid + k * 256;
            if (idx < 2 * RR * H1) sw1[idx] = rw[k];
        }
        if (tid < H1)      sb1[tid] = rb1;
        if (tid < H2)      sb2[tid] = rb2v;
        if (tid < H2 * CC) sw3[tid] = rw3;
    }

    // ---- W23 half: issue row-ct w2 loads BEFORE the sync (overlap) ----
    const int ct = tid - 128;               // valid for tid >= 128
    float4 vrow[H2 / 4];                    // 25 float4 = 100 regs (grid=8, free)
    if (tid >= 128) {
        const float4* __restrict__ w2row =
            reinterpret_cast<const float4*>(w2 + ct * H2);
#pragma unroll
        for (int q = 0; q < H2 / 4; q++)
            vrow[q] = w2row[q];             // 25 independent LDG.128, in flight
    }

    __syncthreads();                        // staging visible; w2 wave still flying

    if (tid < 128) {
        // ===== tournament half: 256 sorted 5-lists -> 1, 8 levels =====
        for (int cnt = GPB; cnt > 1; cnt >>= 1) {
            int half = cnt >> 1;
            if (tid < half) {
                float a[RR], c[RR], o[RR];
#pragma unroll
                for (int j = 0; j < RR; j++) { a[j] = mstop[tid * RR + j]; c[j] = mstop[(tid + half) * RR + j]; }
                merge_desc5(a, c, o);
#pragma unroll
                for (int j = 0; j < RR; j++) mstop[tid * RR + j] = o[j];

#pragma unroll
                for (int j = 0; j < RR; j++) { a[j] = msbot[tid * RR + j]; c[j] = msbot[(tid + half) * RR + j]; }
                merge_asc5(a, c, o);
#pragma unroll
                for (int j = 0; j < RR; j++) msbot[tid * RR + j] = o[j];
            }
            asm volatile("bar.sync 1, 128;" ::: "memory");
        }
        // cat = [min ascending, max descending]
        if (tid < RR)          cat[tid] = msbot[tid];
        else if (tid < 2 * RR) cat[tid] = mstop[tid - RR];
    } else {
        // ===== W23 half: rows ct and ct+128 (concurrent with tournament) =====
        {
            float a0 = 0.0f, a1 = 0.0f;
#pragma unroll
            for (int q = 0; q < H2 / 4; q++) {
                float4 v = vrow[q];
                const int o = q * 4;
                a0 = fmaf(v.x, sw3[(o + 0) * CC + 0], a0);
                a1 = fmaf(v.x, sw3[(o + 0) * CC + 1], a1);
                a0 = fmaf(v.y, sw3[(o + 1) * CC + 0], a0);
                a1 = fmaf(v.y, sw3[(o + 1) * CC + 1], a1);
                a0 = fmaf(v.z, sw3[(o + 2) * CC + 0], a0);
                a1 = fmaf(v.z, sw3[(o + 2) * CC + 1], a1);
                a0 = fmaf(v.w, sw3[(o + 3) * CC + 0], a0);
                a1 = fmaf(v.w, sw3[(o + 3) * CC + 1], a1);
            }
            sW23[ct * CC + 0] = a0;
            sW23[ct * CC + 1] = a1;
        }
        if (ct < H1 - 128) {                // rows 128..199
            const int r2 = ct + 128;
            const float4* __restrict__ w2row2 =
                reinterpret_cast<const float4*>(w2 + r2 * H2);
            float4 v2r[H2 / 4];
#pragma unroll
            for (int q = 0; q < H2 / 4; q++)
                v2r[q] = w2row2[q];         // second batched wave
            float a0 = 0.0f, a1 = 0.0f;
#pragma unroll
            for (int q = 0; q < H2 / 4; q++) {
                float4 v = v2r[q];
                const int o = q * 4;
                a0 = fmaf(v.x, sw3[(o + 0) * CC + 0], a0);
                a1 = fmaf(v.x, sw3[(o + 0) * CC + 1], a1);
                a0 = fmaf(v.y, sw3[(o + 1) * CC + 0], a0);
                a1 = fmaf(v.y, sw3[(o + 1) * CC + 1], a1);
                a0 = fmaf(v.z, sw3[(o + 2) * CC + 0], a0);
                a1 = fmaf(v.z, sw3[(o + 2) * CC + 1], a1);
                a0 = fmaf(v.w, sw3[(o + 3) * CC + 0], a0);
                a1 = fmaf(v.w, sw3[(o + 3) * CC + 1], a1);
            }
            sW23[r2 * CC + 0] = a0;
            sW23[r2 * CC + 1] = a1;
        }
    }

    __syncthreads();   // tournament + full sW23 complete

    // ---- W_eff: 20 outputs x 8 lanes, depth 25 + width-8 shuffle reduce ----
    if (tid < 160) {
        const int g = tid >> 3;
        const int r = tid & 7;
        const int i = g / CC, c = g % CC;
        float s = 0.0f;
#pragma unroll
        for (int k = r; k < H1; k += 8)
            s = fmaf(sw1[i * H1 + k], sW23[k * CC + c], s);
#pragma unroll
        for (int o2 = 4; o2; o2 >>= 1)
            s += __shfl_down_sync(0xffffffff, s, o2, 8);
        if (r == 0) sWe[g] = s;
    }
    // ---- b_eff: 2 channels x 32 lanes, width-32 shuffle reduce ----
    else if (tid < 224) {
        const int c = (tid - 160) >> 5;
        const int l = (tid - 160) & 31;
        float s = 0.0f;
        for (int k = l; k < H1; k += 32)
            s = fmaf(sb1[k], sW23[k * CC + c], s);
        for (int o = l; o < H2; o += 32)
            s = fmaf(sb2[o], sw3[o * CC + c], s);
#pragma unroll
        for (int o2 = 16; o2; o2 >>= 1)
            s += __shfl_down_sync(0xffffffff, s, o2);
        if (l == 0) sbe[c] = s + b3[c];
    }
    __syncthreads();

    // ---- out = cat @ W_eff + b_eff ----
    if (tid < CC) {
        float a = sbe[tid];
#pragma unroll
        for (int i = 0; i < 2 * RR; i++)
            a = fmaf(cat[i], sWe[i * CC + tid], a);
        out[b * CC + tid] = a;
    }
}

// ---------------------------------------------------------------------------
extern "C" void kernel_launch(void* const* d_in, const int* in_sizes, int n_in,
                              void* d_out, int out_size)
{
    const float* x      = (const float*)d_in[0];
    const float* conv_w = (const float*)d_in[1];
    const float* conv_b = (const float*)d_in[2];
    const float* w1     = (const float*)d_in[3];
    const float* b1     = (const float*)d_in[4];
    const float* w2     = (const float*)d_in[5];
    const float* b2     = (const float*)d_in[6];
    const float* w3     = (const float*)d_in[7];
    const float* b3     = (const float*)d_in[8];
    float* out          = (float*)d_out;

    dim3 grid(GPB, BB);
    chowder_scores_topk_kernel<<<grid, 256>>>(x, conv_w, conv_b);
    chowder_merge_mlp_kernel<<<BB, 256>>>(w1, b1, w2, b2, w3, b3, out);
}